// round 1
// baseline (speedup 1.0000x reference)
#include <cuda_runtime.h>
#include <cstdint>

// Problem constants (fixed by the reference)
#define BATCH 8
#define CIN   128
#define OUTC  128
#define T_IN  32768
#define P_OUT 32769          // T+1 output positions
#define NTILE 128            // positions per block
#define WPAD  130            // sW inner pad: conflict-free + 8B aligned rows
#define XPAD  132            // sX inner pad

// ---- packed f32x2 helpers (sm_103a) ----
__device__ __forceinline__ unsigned long long pack2(float a, float b) {
    unsigned long long r;
    asm("mov.b64 %0, {%1, %2};" : "=l"(r) : "f"(a), "f"(b));
    return r;
}
__device__ __forceinline__ void fma2(unsigned long long& d,
                                     unsigned long long a,
                                     unsigned long long b) {
    asm("fma.rn.f32x2 %0, %1, %2, %0;" : "+l"(d) : "l"(a), "l"(b));
}
__device__ __forceinline__ float2 unpack2(unsigned long long v) {
    float2 r;
    asm("mov.b64 {%0, %1}, %2;" : "=f"(r.x), "=f"(r.y) : "l"(v));
    return r;
}

// Grid: (ceil(P_OUT/NTILE)=257, BATCH). Block: 256 threads.
// Per block: out[b, 0..127, p0..p0+127] = W0 @ x(p) + W1 @ x(p+2) + bias
__global__ __launch_bounds__(256, 1)
void dconv_kernel(const float* __restrict__ x,
                  const float* __restrict__ W,
                  const float* __restrict__ bias,
                  float* __restrict__ out)
{
    extern __shared__ float smem[];
    float* sW = smem;                          // [2][CIN][WPAD]
    float* sX = smem + 2 * CIN * WPAD;         // [CIN][XPAD], valid cols 0..129

    const int tid = threadIdx.x;
    const int b   = blockIdx.y;
    const long p0 = (long)blockIdx.x * NTILE;

    // ---- stage W: global [o][c][k] -> smem sW[k][c][o] ----
    // 32768 floats = 8192 float4; each float4 covers (c,k=0),(c,k=1),(c+1,0),(c+1,1)
    const float4* W4 = reinterpret_cast<const float4*>(W);
    #pragma unroll 4
    for (int it = 0; it < 32; ++it) {
        int gidx = it * 256 + tid;
        float4 f = W4[gidx];
        int L = gidx * 4;
        int o = L >> 8;                // same o for whole float4 (256 % 4 == 0)
        int c = (L & 255) >> 1;
        sW[(0 * CIN + c    ) * WPAD + o] = f.x;
        sW[(1 * CIN + c    ) * WPAD + o] = f.y;
        sW[(0 * CIN + c + 1) * WPAD + o] = f.z;
        sW[(1 * CIN + c + 1) * WPAD + o] = f.w;
    }

    // ---- stage x tile: sX[c][j] = x[b,c,p0+j], j in [0,130), zero past T ----
    {
        const float* xb = x + (size_t)b * CIN * T_IN;
        for (int idx = tid; idx < CIN * 130; idx += 256) {
            int c = idx / 130;
            int j = idx - c * 130;
            long p = p0 + j;
            sX[c * XPAD + j] = (p < T_IN) ? xb[(size_t)c * T_IN + p] : 0.0f;
        }
    }
    __syncthreads();

    // ---- compute: per thread 8 (M, as 4 f32x2 pairs) x 8 (N) micro-tile ----
    const int tx = tid & 15;    // N:   positions p0 + tx*8 .. +7
    const int ty = tid >> 4;    // M:   outputs  ty*8 .. +7

    unsigned long long acc[4][8];
    #pragma unroll
    for (int mj = 0; mj < 4; ++mj)
        #pragma unroll
        for (int ni = 0; ni < 8; ++ni)
            acc[mj][ni] = 0ull;   // packed {0.0f, 0.0f}

    #pragma unroll 4
    for (int c = 0; c < CIN; ++c) {
        // W pairs along M come directly as 64-bit smem loads (rows 8B-aligned)
        const unsigned long long* w0r =
            reinterpret_cast<const unsigned long long*>(sW + (0 * CIN + c) * WPAD + ty * 8);
        const unsigned long long* w1r =
            reinterpret_cast<const unsigned long long*>(sW + (1 * CIN + c) * WPAD + ty * 8);
        unsigned long long w0[4], w1[4];
        #pragma unroll
        for (int mj = 0; mj < 4; ++mj) { w0[mj] = w0r[mj]; w1[mj] = w1r[mj]; }

        // x values: positions tx*8 .. tx*8+9 (the +2 halo for the k=1 tap)
        const float* xr = sX + c * XPAD + tx * 8;
        float xv[10];
        float4 v0 = *reinterpret_cast<const float4*>(xr);
        float4 v1 = *reinterpret_cast<const float4*>(xr + 4);
        xv[0] = v0.x; xv[1] = v0.y; xv[2] = v0.z; xv[3] = v0.w;
        xv[4] = v1.x; xv[5] = v1.y; xv[6] = v1.z; xv[7] = v1.w;
        xv[8] = xr[8]; xv[9] = xr[9];

        unsigned long long xb2[10];
        #pragma unroll
        for (int j = 0; j < 10; ++j) xb2[j] = pack2(xv[j], xv[j]);

        #pragma unroll
        for (int mj = 0; mj < 4; ++mj) {
            #pragma unroll
            for (int ni = 0; ni < 8; ++ni) {
                fma2(acc[mj][ni], w0[mj], xb2[ni]);      // W0 * x(p)
                fma2(acc[mj][ni], w1[mj], xb2[ni + 2]);  // W1 * x(p+2)
            }
        }
    }

    // ---- epilogue: add bias, store (rows are odd-length -> scalar stores) ----
    #pragma unroll
    for (int mj = 0; mj < 4; ++mj) {
        int o0 = ty * 8 + 2 * mj;
        float b0 = bias[o0];
        float b1 = bias[o0 + 1];
        size_t base0 = ((size_t)b * OUTC + o0) * P_OUT + (size_t)p0 + tx * 8;
        size_t base1 = base0 + P_OUT;
        #pragma unroll
        for (int ni = 0; ni < 8; ++ni) {
            long p = p0 + tx * 8 + ni;
            if (p < P_OUT) {
                float2 v = unpack2(acc[mj][ni]);
                out[base0 + ni] = v.x + b0;
                out[base1 + ni] = v.y + b1;
            }
        }
    }
}

extern "C" void kernel_launch(void* const* d_in, const int* in_sizes, int n_in,
                              void* d_out, int out_size)
{
    const float* x  = (const float*)d_in[0];   // (8, 128, 32768) f32
    const float* W  = (const float*)d_in[1];   // (128, 128, 2)   f32
    const float* bs = (const float*)d_in[2];   // (128,)          f32
    float* out = (float*)d_out;                // (8, 128, 32769) f32

    const size_t smem_bytes = (size_t)(2 * CIN * WPAD + CIN * XPAD) * sizeof(float); // 200704 B
    cudaFuncSetAttribute(dconv_kernel, cudaFuncAttributeMaxDynamicSharedMemorySize,
                         (int)smem_bytes);

    dim3 grid((P_OUT + NTILE - 1) / NTILE, BATCH);   // (257, 8)
    dim3 block(256);
    dconv_kernel<<<grid, block, smem_bytes>>>(x, W, bs, out);
}

// round 3
// speedup vs baseline: 2.2609x; 2.2609x over previous
#include <cuda_runtime.h>
#include <cuda_bf16.h>
#include <cstdint>

#define BATCH  8
#define CIN    128
#define OUTC   128
#define T_IN   32768
#define P_OUT  32769
#define NTILE  128           // positions (GEMM M) per CTA
#define XPITCH 132           // f32 pitch: conflict-free
#define WPITCH 132           // u32 pitch: conflict-free

// smem byte offsets
#define SM_XF   0                       // float [128][132]  = 67584 B
#define SM_WH   67584                   // u32   [128][132]  = 67584 B
#define SM_WL   135168                  // u32   [128][132]  = 67584 B
#define SM_BIAS 202752                  // float [128]
#define SM_TOT  203264

// Pre-baked W pair images: [kappa/2][o] of bf16x2 {W[o][2c] lo-half, W[o][2c+1] hi-half}
__device__ __align__(16) uint32_t g_Wh[128 * WPITCH];
__device__ __align__(16) uint32_t g_Wl[128 * WPITCH];

__device__ __forceinline__ uint32_t cvt2(float hi, float lo) {
    uint32_t r;
    asm("cvt.rn.bf16x2.f32 %0, %1, %2;" : "=r"(r) : "f"(hi), "f"(lo));
    return r;
}
__device__ __forceinline__ uint32_t lo_resid(uint32_t h, float xhi, float xlo) {
    float fh = __uint_as_float(h & 0xffff0000u);   // hi half back to f32 (exact)
    float fl = __uint_as_float(h << 16);           // lo half
    return cvt2(xhi - fh, xlo - fl);
}
__device__ __forceinline__ void mma16816(float* d, const uint32_t* a, uint32_t b0, uint32_t b1) {
    asm volatile(
        "mma.sync.aligned.m16n8k16.row.col.f32.bf16.bf16.f32 "
        "{%0,%1,%2,%3}, {%4,%5,%6,%7}, {%8,%9}, {%0,%1,%2,%3};"
        : "+f"(d[0]), "+f"(d[1]), "+f"(d[2]), "+f"(d[3])
        : "r"(a[0]), "r"(a[1]), "r"(a[2]), "r"(a[3]), "r"(b0), "r"(b1));
}

// ---- prep: split W into bf16 hi/lo pair images (runs once per launch, tiny) ----
__global__ void prep_W(const float* __restrict__ W) {
    int idx = blockIdx.x * blockDim.x + threadIdx.x;   // 16384
    int cp = idx >> 7;            // kappa-pair index 0..127
    int o  = idx & 127;
    float w0 = W[o * 256 + 2 * cp];       // kappa = 2cp   (tap 0)
    float w1 = W[o * 256 + 2 * cp + 1];   // kappa = 2cp+1 (tap 1)
    uint32_t h = cvt2(w1, w0);
    uint32_t l = lo_resid(h, w1, w0);
    g_Wh[cp * WPITCH + o] = h;
    g_Wl[cp * WPITCH + o] = l;
}

// ---- main: one 128-position x 128-output tile per CTA, 8 warps ----
__global__ __launch_bounds__(256, 1)
void dconv_hmma(const float* __restrict__ x,
                const float* __restrict__ bias,
                float* __restrict__ out)
{
    extern __shared__ char smem[];
    float*    sXf   = reinterpret_cast<float*>(smem + SM_XF);
    uint32_t* sWh   = reinterpret_cast<uint32_t*>(smem + SM_WH);
    uint32_t* sWl   = reinterpret_cast<uint32_t*>(smem + SM_WL);
    float*    sBias = reinterpret_cast<float*>(smem + SM_BIAS);

    const int tid = threadIdx.x;
    const int b   = blockIdx.y;
    const long p0 = (long)blockIdx.x * NTILE;

    // stage x tile: sXf[c][j] = x[b,c,p0+j], j in [0,130)
    const float* xb = x + (size_t)b * CIN * T_IN;
    if (p0 + 132 <= T_IN) {
        #pragma unroll 4
        for (int i = tid; i < 128 * 33; i += 256) {
            int c = i / 33, ch = i - c * 33;
            float4 v = *reinterpret_cast<const float4*>(xb + (size_t)c * T_IN + p0 + ch * 4);
            *reinterpret_cast<float4*>(sXf + c * XPITCH + ch * 4) = v;
        }
    } else {
        for (int i = tid; i < 128 * 130; i += 256) {
            int c = i / 130, j = i - c * 130;
            long p = p0 + j;
            sXf[c * XPITCH + j] = (p < T_IN) ? xb[(size_t)c * T_IN + p] : 0.0f;
        }
    }
    // stage W hi/lo images (L2-hot)
    {
        const uint4* sh = reinterpret_cast<const uint4*>(g_Wh);
        const uint4* sl = reinterpret_cast<const uint4*>(g_Wl);
        uint4* dh = reinterpret_cast<uint4*>(sWh);
        uint4* dl = reinterpret_cast<uint4*>(sWl);
        #pragma unroll 4
        for (int i = tid; i < 4224; i += 256) { dh[i] = sh[i]; dl[i] = sl[i]; }
    }
    if (tid < 128) sBias[tid] = bias[tid];
    __syncthreads();

    const int lane = tid & 31;
    const int t = lane & 3;         // threadID_in_group
    const int g = lane >> 2;        // groupID
    const int warp = tid >> 5;
    const int mb = (warp >> 2) * 64;    // warp M base (positions)
    const int nb = (warp & 3) * 32;     // warp N base (outputs)

    float acc[4][4][4];
    #pragma unroll
    for (int mf = 0; mf < 4; ++mf)
        #pragma unroll
        for (int nf = 0; nf < 4; ++nf)
            #pragma unroll
            for (int i = 0; i < 4; ++i) acc[mf][nf][i] = 0.0f;

    #pragma unroll 1
    for (int k = 0; k < 16; ++k) {
        const int r0 = 8 * k + t;           // kappa-pair row
        // B fragments (hi & lo) — one 4B LDS each, conflict-free
        uint32_t bh0[4], bh1[4], bl0[4], bl1[4];
        #pragma unroll
        for (int nf = 0; nf < 4; ++nf) {
            int o = nb + nf * 8 + g;
            bh0[nf] = sWh[r0 * WPITCH + o];
            bh1[nf] = sWh[(r0 + 4) * WPITCH + o];
            bl0[nf] = sWl[r0 * WPITCH + o];
            bl1[nf] = sWl[(r0 + 4) * WPITCH + o];
        }
        #pragma unroll
        for (int mf = 0; mf < 4; ++mf) {
            // A fragment: c0 = 8k+t, c1 = c0+4; rows p0..: g, g+8; taps at +0 / +2
            const float* pa = sXf + r0 * XPITCH + (mb + mf * 16 + g);
            float x00 = pa[0], x02 = pa[2], x08 = pa[8], x0a = pa[10];
            const float* pb = pa + 4 * XPITCH;
            float x10 = pb[0], x12 = pb[2], x18 = pb[8], x1a = pb[10];
            uint32_t ah[4], al[4];
            ah[0] = cvt2(x02, x00);  al[0] = lo_resid(ah[0], x02, x00);
            ah[1] = cvt2(x0a, x08);  al[1] = lo_resid(ah[1], x0a, x08);
            ah[2] = cvt2(x12, x10);  al[2] = lo_resid(ah[2], x12, x10);
            ah[3] = cvt2(x1a, x18);  al[3] = lo_resid(ah[3], x1a, x18);
            #pragma unroll
            for (int nf = 0; nf < 4; ++nf) {
                mma16816(acc[mf][nf], ah, bh0[nf], bh1[nf]);   // Ahi*Bhi
                mma16816(acc[mf][nf], al, bh0[nf], bh1[nf]);   // Alo*Bhi
                mma16816(acc[mf][nf], ah, bl0[nf], bl1[nf]);   // Ahi*Blo
            }
        }
    }

    // epilogue: d rows = positions (g, g+8), cols = outputs (2t, 2t+1)
    #pragma unroll
    for (int mf = 0; mf < 4; ++mf) {
        long pg = p0 + mb + mf * 16 + g;
        #pragma unroll
        for (int nf = 0; nf < 4; ++nf) {
            int o = nb + nf * 8 + 2 * t;
            float b0 = sBias[o], b1 = sBias[o + 1];
            float* ob = out + ((size_t)b * OUTC + o) * P_OUT + pg;
            if (pg < P_OUT) {
                ob[0]     = acc[mf][nf][0] + b0;
                ob[P_OUT] = acc[mf][nf][1] + b1;
            }
            if (pg + 8 < P_OUT) {
                ob[8]         = acc[mf][nf][2] + b0;
                ob[P_OUT + 8] = acc[mf][nf][3] + b1;
            }
        }
    }
}

extern "C" void kernel_launch(void* const* d_in, const int* in_sizes, int n_in,
                              void* d_out, int out_size)
{
    const float* x  = (const float*)d_in[0];   // (8, 128, 32768)
    const float* W  = (const float*)d_in[1];   // (128, 128, 2)
    const float* bs = (const float*)d_in[2];   // (128,)
    float* out = (float*)d_out;                // (8, 128, 32769)

    cudaFuncSetAttribute(dconv_hmma, cudaFuncAttributeMaxDynamicSharedMemorySize, SM_TOT);

    prep_W<<<64, 256>>>(W);
    dim3 grid((P_OUT + NTILE - 1) / NTILE, BATCH);   // (257, 8)
    dconv_hmma<<<grid, 256, SM_TOT>>>(x, bs, out);
}

// round 4
// speedup vs baseline: 2.4786x; 1.0963x over previous
#include <cuda_runtime.h>
#include <cuda_bf16.h>
#include <cstdint>

#define BATCH  8
#define CIN    128
#define OUTC   128
#define T_IN   32768
#define P_OUT  32769
#define NTILE  128

#define WPITCH 132    // u64 pitch for W pair rows (132 % 16 == 4 -> conflict-free LDS.64)
#define APITCH 136    // u32 pitch for A images    (136 % 32 == 8 -> conflict-free LDS.32)

// smem byte offsets
#define SM_W    0                        // u64 [2][64][WPITCH] = 135168 B (hi image, then lo)
#define SM_AH   135168                   // u32 [64][APITCH]    = 34816 B
#define SM_AL   (SM_AH + 34816)          // 169984
#define SM_BIAS (SM_AL + 34816)          // 204800
#define SM_TOT  (SM_BIAS + 512)          // 205312

// Pre-baked W image, exact smem layout: [hi|lo][pr][o], entry = {row r (lo u32), row r+4 (hi u32)}
__device__ __align__(16) unsigned long long g_W64[2 * 64 * WPITCH];

__device__ __forceinline__ uint32_t cvt2(float hi, float lo) {
    uint32_t r;
    asm("cvt.rn.bf16x2.f32 %0, %1, %2;" : "=r"(r) : "f"(hi), "f"(lo));
    return r;
}
__device__ __forceinline__ uint32_t lo_resid(uint32_t h, float xhi, float xlo) {
    float fh = __uint_as_float(h & 0xffff0000u);
    float fl = __uint_as_float(h << 16);
    return cvt2(xhi - fh, xlo - fl);
}
__device__ __forceinline__ void mma16816(float* d, const uint32_t* a, uint32_t b0, uint32_t b1) {
    asm volatile(
        "mma.sync.aligned.m16n8k16.row.col.f32.bf16.bf16.f32 "
        "{%0,%1,%2,%3}, {%4,%5,%6,%7}, {%8,%9}, {%0,%1,%2,%3};"
        : "+f"(d[0]), "+f"(d[1]), "+f"(d[2]), "+f"(d[3])
        : "r"(a[0]), "r"(a[1]), "r"(a[2]), "r"(a[3]), "r"(b0), "r"(b1));
}

// ---- prep: bake W into paired-row u64 hi/lo images (8192 threads) ----
__global__ void prep_W(const float* __restrict__ W) {
    int idx = blockIdx.x * blockDim.x + threadIdx.x;   // 8192
    int pr = idx >> 7;            // 0..63
    int o  = idx & 127;
    int r  = ((pr >> 2) << 3) | (pr & 3);   // rows r and r+4 of the kappa-pair matrix
    float w0a = W[o * 256 + 2 * r],       w1a = W[o * 256 + 2 * r + 1];
    float w0b = W[o * 256 + 2 * (r + 4)], w1b = W[o * 256 + 2 * (r + 4) + 1];
    uint32_t ha = cvt2(w1a, w0a), la = lo_resid(ha, w1a, w0a);
    uint32_t hb = cvt2(w1b, w0b), lb = lo_resid(hb, w1b, w0b);
    g_W64[pr * WPITCH + o]               = ((unsigned long long)hb << 32) | ha;
    g_W64[64 * WPITCH + pr * WPITCH + o] = ((unsigned long long)lb << 32) | la;
}

// ---- main: 512 threads, 16 warps, tile M=128 x N=128 x K=256 (2 halves) ----
__global__ __launch_bounds__(512, 1)
void dconv_hmma2(const float* __restrict__ x,
                 const float* __restrict__ bias,
                 float* __restrict__ out)
{
    extern __shared__ char smem[];
    unsigned long long* sW64 = reinterpret_cast<unsigned long long*>(smem + SM_W);
    uint32_t* sAh   = reinterpret_cast<uint32_t*>(smem + SM_AH);
    uint32_t* sAl   = reinterpret_cast<uint32_t*>(smem + SM_AL);
    float*    sBias = reinterpret_cast<float*>(smem + SM_BIAS);

    const int tid = threadIdx.x;
    const int b   = blockIdx.y;
    const long p0 = (long)blockIdx.x * NTILE;
    const bool fast = (p0 + 130 <= T_IN);

    // ---- W copy (L2-hot, 135168 B as uint4) + bias ----
    {
        const uint4* src = reinterpret_cast<const uint4*>(g_W64);
        uint4* dst = reinterpret_cast<uint4*>(sW64);
        #pragma unroll 4
        for (int i = tid; i < 8448; i += 512) dst[i] = src[i];
    }
    if (tid < 128) sBias[tid] = bias[tid];

    const int lane = tid & 31;
    const int t = lane & 3;
    const int g = lane >> 2;
    const int warp = tid >> 5;
    const int mb = (warp >> 2) * 32;   // M base (positions)
    const int nb = (warp & 3) * 32;    // N base (outputs)

    float acc[2][4][4];
    #pragma unroll
    for (int mf = 0; mf < 2; ++mf)
        #pragma unroll
        for (int nf = 0; nf < 4; ++nf)
            #pragma unroll
            for (int i = 0; i < 4; ++i) acc[mf][nf][i] = 0.0f;

    const float* xbase = x + (size_t)b * CIN * T_IN;

    #pragma unroll 1
    for (int h = 0; h < 2; ++h) {
        // ---- build A half h: pair images for c in [64h, 64h+64) ----
        if (h) __syncthreads();           // all warps done reading previous half
        if (fast) {
            const int c_l = tid >> 3, chunk = tid & 7;
            const float* gx = xbase + (size_t)(64 * h + c_l) * T_IN + p0 + chunk * 16;
            float v[18];
            float4 q0 = *reinterpret_cast<const float4*>(gx);
            float4 q1 = *reinterpret_cast<const float4*>(gx + 4);
            float4 q2 = *reinterpret_cast<const float4*>(gx + 8);
            float4 q3 = *reinterpret_cast<const float4*>(gx + 12);
            v[0]=q0.x; v[1]=q0.y; v[2]=q0.z; v[3]=q0.w;
            v[4]=q1.x; v[5]=q1.y; v[6]=q1.z; v[7]=q1.w;
            v[8]=q2.x; v[9]=q2.y; v[10]=q2.z; v[11]=q2.w;
            v[12]=q3.x; v[13]=q3.y; v[14]=q3.z; v[15]=q3.w;
            v[16]=gx[16]; v[17]=gx[17];
            uint32_t* dh = sAh + c_l * APITCH + chunk * 16;
            uint32_t* dl = sAl + c_l * APITCH + chunk * 16;
            #pragma unroll
            for (int j = 0; j < 16; j += 2) {
                uint32_t h0 = cvt2(v[j+2], v[j]);
                uint32_t h1 = cvt2(v[j+3], v[j+1]);
                uint32_t l0 = lo_resid(h0, v[j+2], v[j]);
                uint32_t l1 = lo_resid(h1, v[j+3], v[j+1]);
                *reinterpret_cast<unsigned long long*>(dh + j) = ((unsigned long long)h1 << 32) | h0;
                *reinterpret_cast<unsigned long long*>(dl + j) = ((unsigned long long)l1 << 32) | l0;
            }
        } else {
            for (int i = tid; i < 64 * 128; i += 512) {
                int c_l = i >> 7, p = i & 127;
                const float* gx = xbase + (size_t)(64 * h + c_l) * T_IN;
                long pp = p0 + p;
                float x0 = (pp < T_IN) ? gx[pp] : 0.0f;
                float x2 = (pp + 2 < T_IN) ? gx[pp + 2] : 0.0f;
                uint32_t hh = cvt2(x2, x0);
                sAh[c_l * APITCH + p] = hh;
                sAl[c_l * APITCH + p] = lo_resid(hh, x2, x0);
            }
        }
        __syncthreads();

        // ---- compute 8 k-steps of this half ----
        #pragma unroll 1
        for (int kl = 0; kl < 8; ++kl) {
            const int pr = (h << 5) + (kl << 2) + t;          // global W pair-row
            const unsigned long long* wr = sW64 + (size_t)pr * WPITCH;
            unsigned long long wh[4], wl[4];
            #pragma unroll
            for (int nf = 0; nf < 4; ++nf) {
                int o = nb + nf * 8 + g;
                wh[nf] = wr[o];
                wl[nf] = wr[64 * WPITCH + o];
            }
            const int lr = (kl << 3) + t;                     // local A row
            const uint32_t* arh = sAh + lr * APITCH;
            const uint32_t* arl = sAl + lr * APITCH;
            #pragma unroll
            for (int mf = 0; mf < 2; ++mf) {
                const int pos = mb + mf * 16 + g;
                uint32_t ah[4], al[4];
                ah[0] = arh[pos];                ah[1] = arh[pos + 8];
                ah[2] = arh[pos + 4 * APITCH];   ah[3] = arh[pos + 8 + 4 * APITCH];
                al[0] = arl[pos];                al[1] = arl[pos + 8];
                al[2] = arl[pos + 4 * APITCH];   al[3] = arl[pos + 8 + 4 * APITCH];
                #pragma unroll
                for (int nf = 0; nf < 4; ++nf) {
                    uint32_t bh0 = (uint32_t)wh[nf], bh1 = (uint32_t)(wh[nf] >> 32);
                    mma16816(acc[mf][nf], ah, bh0, bh1);                                   // Ahi*Bhi
                    mma16816(acc[mf][nf], al, bh0, bh1);                                   // Alo*Bhi
                    mma16816(acc[mf][nf], ah, (uint32_t)wl[nf], (uint32_t)(wl[nf] >> 32)); // Ahi*Blo
                }
            }
        }
    }

    // ---- epilogue ----
    #pragma unroll
    for (int mf = 0; mf < 2; ++mf) {
        long pg = p0 + mb + mf * 16 + g;
        #pragma unroll
        for (int nf = 0; nf < 4; ++nf) {
            int o = nb + nf * 8 + 2 * t;
            float b0 = sBias[o], b1 = sBias[o + 1];
            float* ob = out + ((size_t)b * OUTC + o) * P_OUT + pg;
            if (pg < P_OUT) {
                ob[0]     = acc[mf][nf][0] + b0;
                ob[P_OUT] = acc[mf][nf][1] + b1;
            }
            if (pg + 8 < P_OUT) {
                ob[8]         = acc[mf][nf][2] + b0;
                ob[P_OUT + 8] = acc[mf][nf][3] + b1;
            }
        }
    }
}

extern "C" void kernel_launch(void* const* d_in, const int* in_sizes, int n_in,
                              void* d_out, int out_size)
{
    const float* x  = (const float*)d_in[0];   // (8, 128, 32768)
    const float* W  = (const float*)d_in[1];   // (128, 128, 2)
    const float* bs = (const float*)d_in[2];   // (128,)
    float* out = (float*)d_out;                // (8, 128, 32769)

    cudaFuncSetAttribute(dconv_hmma2, cudaFuncAttributeMaxDynamicSharedMemorySize, SM_TOT);

    prep_W<<<32, 256>>>(W);
    dim3 grid((P_OUT + NTILE - 1) / NTILE, BATCH);   // (257, 8)
    dconv_hmma2<<<grid, 512, SM_TOT>>>(x, bs, out);
}

// round 6
// speedup vs baseline: 2.8506x; 1.1501x over previous
#include <cuda_runtime.h>
#include <cuda_bf16.h>
#include <cstdint>

#define BATCH  8
#define CIN    128
#define OUTC   128
#define T_IN   32768
#define P_OUT  32769
#define NTILES 2056          // 257 p-tiles * 8 batches
#define GRIDX  152

#define WP 132               // u64 pitch, W image rows
#define AP 132               // u64 pitch, A image rows

// smem byte offsets
#define SM_W    0                        // u64 [128][WP]  = 135168
#define SM_A0   135168                   // u64 [32][AP]   = 33792
#define SM_A1   168960                   // u64 [32][AP]   = 33792
#define SM_BIAS 202752
#define SM_TOT  203264

// W image: [channel r][o] u64 = { lo32: bf16x2(hi(w1),hi(w0)), hi32: residual pair }
__device__ __align__(16) unsigned long long g_W64[128 * WP];

typedef unsigned long long u64;

__device__ __forceinline__ uint32_t cvt2(float hi, float lo) {
    uint32_t r;
    asm("cvt.rn.bf16x2.f32 %0, %1, %2;" : "=r"(r) : "f"(hi), "f"(lo));
    return r;
}
__device__ __forceinline__ uint32_t lo_resid(uint32_t h, float xhi, float xlo) {
    float fh = __uint_as_float(h & 0xffff0000u);
    float fl = __uint_as_float(h << 16);
    return cvt2(xhi - fh, xlo - fl);
}
__device__ __forceinline__ void mma16816(float* d, const uint32_t* a, uint32_t b0, uint32_t b1) {
    asm volatile(
        "mma.sync.aligned.m16n8k16.row.col.f32.bf16.bf16.f32 "
        "{%0,%1,%2,%3}, {%4,%5,%6,%7}, {%8,%9}, {%0,%1,%2,%3};"
        : "+f"(d[0]), "+f"(d[1]), "+f"(d[2]), "+f"(d[3])
        : "r"(a[0]), "r"(a[1]), "r"(a[2]), "r"(a[3]), "r"(b0), "r"(b1));
}

__global__ void prep_W(const float* __restrict__ W) {
    int idx = blockIdx.x * blockDim.x + threadIdx.x;   // 16384
    int r = idx >> 7;            // channel 0..127
    int o = idx & 127;
    float w0 = W[o * 256 + 2 * r];
    float w1 = W[o * 256 + 2 * r + 1];
    uint32_t h = cvt2(w1, w0);
    uint32_t l = lo_resid(h, w1, w0);
    g_W64[r * WP + o] = ((u64)l << 32) | h;
}

// ---- LDG: thread (row, q) loads x window [p0+8q, p0+8q+10) for channel c*32+row ----
__device__ __forceinline__ void ldg_chunk(const float* __restrict__ x,
                                          int tile, int c, int row, int q, float* v) {
    int b = tile & 7;
    long p0 = (long)(tile >> 3) * 128;
    const float* gxr = x + (size_t)b * CIN * T_IN + (size_t)(c * 32 + row) * T_IN;
    long pb = p0 + 8 * q;                 // 16B-aligned (p0 mult of 128, 8q mult of 4 floats... 8q*4B=32B)
    if (p0 + 130 <= T_IN) {
        float4 q0 = *reinterpret_cast<const float4*>(gxr + pb);
        float4 q1 = *reinterpret_cast<const float4*>(gxr + pb + 4);
        v[0]=q0.x; v[1]=q0.y; v[2]=q0.z; v[3]=q0.w;
        v[4]=q1.x; v[5]=q1.y; v[6]=q1.z; v[7]=q1.w;
        v[8]=gxr[pb + 8]; v[9]=gxr[pb + 9];
    } else {
        #pragma unroll
        for (int k = 0; k < 10; ++k) {
            long p = pb + k;
            v[k] = (p < T_IN) ? gxr[p] : 0.0f;
        }
    }
}

// ---- cvt + STS: positions [8q, 8q+8), pair(p) = {x[p], x[p+2]} hi|lo packed u64 ----
__device__ __forceinline__ void sts_chunk(u64* __restrict__ buf, int row, int q, const float* v) {
    #pragma unroll
    for (int j = 0; j < 4; ++j) {
        uint32_t h0 = cvt2(v[2*j + 2], v[2*j]);
        uint32_t l0 = lo_resid(h0, v[2*j + 2], v[2*j]);
        uint32_t h1 = cvt2(v[2*j + 3], v[2*j + 1]);
        uint32_t l1 = lo_resid(h1, v[2*j + 3], v[2*j + 1]);
        uint4 val; val.x = h0; val.y = l0; val.z = h1; val.w = l1;
        *reinterpret_cast<uint4*>(buf + (size_t)row * AP + 8 * q + 2 * j) = val;  // 16B-aligned
    }
}

__global__ __launch_bounds__(512, 1)
void dconv6(const float* __restrict__ x,
            const float* __restrict__ bias,
            float* __restrict__ out)
{
    extern __shared__ char smem[];
    u64*   sW    = reinterpret_cast<u64*>(smem + SM_W);
    u64*   sA[2] = { reinterpret_cast<u64*>(smem + SM_A0),
                     reinterpret_cast<u64*>(smem + SM_A1) };
    float* sBias = reinterpret_cast<float*>(smem + SM_BIAS);

    const int tid = threadIdx.x;
    const int lane = tid & 31;
    const int t = lane & 3;
    const int g = lane >> 2;
    const int warp = tid >> 5;
    const int mb = (warp >> 2) * 32;
    const int nb = (warp & 3) * 32;
    const int arow = tid >> 4;     // staging: channel-within-chunk 0..31
    const int aq   = tid & 15;     // staging: 8-position group 0..15

    // ---- one-time: W image + bias to smem ----
    {
        const uint4* src = reinterpret_cast<const uint4*>(g_W64);
        uint4* dst = reinterpret_cast<uint4*>(sW);
        #pragma unroll 4
        for (int i = tid; i < 8448; i += 512) dst[i] = src[i];
    }
    if (tid < 128) sBias[tid] = bias[tid];

    float acc[2][4][4];
    #pragma unroll
    for (int mf = 0; mf < 2; ++mf)
        #pragma unroll
        for (int nf = 0; nf < 4; ++nf)
            #pragma unroll
            for (int i = 0; i < 4; ++i) acc[mf][nf][i] = 0.0f;

    int tile = blockIdx.x;
    if (tile < NTILES) {
        float v[10];
        ldg_chunk(x, tile, 0, arow, aq, v);
        sts_chunk(sA[0], arow, aq, v);
    }
    __syncthreads();

    while (tile < NTILES) {
        const int ntile = tile + GRIDX;
        const bool hn = ntile < NTILES;

        #pragma unroll
        for (int c = 0; c < 4; ++c) {
            // -- LDG next chunk (or next tile's chunk 0) --
            float v[10];
            #pragma unroll
            for (int k = 0; k < 10; ++k) v[k] = 0.0f;
            if (c < 3)      ldg_chunk(x, tile,  c + 1, arow, aq, v);
            else if (hn)    ldg_chunk(x, ntile, 0,     arow, aq, v);

            // -- MMA chunk c from buf (c&1) --
            {
                const u64* Ab = sA[c & 1];
                #pragma unroll
                for (int kl = 0; kl < 4; ++kl) {
                    const int lrt = 8 * kl + t;
                    const u64* wr = sW + (size_t)(32 * c + lrt) * WP;
                    u64 w0[4], w1[4];
                    #pragma unroll
                    for (int nf = 0; nf < 4; ++nf) {
                        int o = nb + nf * 8 + g;
                        w0[nf] = wr[o];
                        w1[nf] = wr[4 * WP + o];
                    }
                    const u64* ar = Ab + (size_t)lrt * AP;
                    #pragma unroll
                    for (int mf = 0; mf < 2; ++mf) {
                        const int pos = mb + mf * 16 + g;
                        u64 a0 = ar[pos],          a1 = ar[pos + 8];
                        u64 a2 = ar[4 * AP + pos], a3 = ar[4 * AP + pos + 8];
                        uint32_t ah[4] = { (uint32_t)a0, (uint32_t)a1, (uint32_t)a2, (uint32_t)a3 };
                        uint32_t al[4] = { (uint32_t)(a0 >> 32), (uint32_t)(a1 >> 32),
                                           (uint32_t)(a2 >> 32), (uint32_t)(a3 >> 32) };
                        #pragma unroll
                        for (int nf = 0; nf < 4; ++nf) {
                            uint32_t bh0 = (uint32_t)w0[nf], bl0 = (uint32_t)(w0[nf] >> 32);
                            uint32_t bh1 = (uint32_t)w1[nf], bl1 = (uint32_t)(w1[nf] >> 32);
                            mma16816(acc[mf][nf], ah, bh0, bh1);   // Ahi*Bhi
                            mma16816(acc[mf][nf], al, bh0, bh1);   // Alo*Bhi
                            mma16816(acc[mf][nf], ah, bl0, bl1);   // Ahi*Blo
                        }
                    }
                }
            }

            // -- cvt + STS next chunk into buf ((c+1)&1) --
            if (c < 3 || hn) sts_chunk(sA[(c + 1) & 1], arow, aq, v);
            __syncthreads();
        }

        // ---- epilogue for this tile (next tile's chunk-0 already staged) ----
        {
            const int b = tile & 7;
            const long p0 = (long)(tile >> 3) * 128;
            #pragma unroll
            for (int mf = 0; mf < 2; ++mf) {
                long pg = p0 + mb + mf * 16 + g;
                #pragma unroll
                for (int nf = 0; nf < 4; ++nf) {
                    int o = nb + nf * 8 + 2 * t;
                    float b0 = sBias[o], b1 = sBias[o + 1];
                    float* ob = out + ((size_t)b * OUTC + o) * P_OUT + pg;
                    if (pg < P_OUT) {
                        ob[0]     = acc[mf][nf][0] + b0;
                        ob[P_OUT] = acc[mf][nf][1] + b1;
                    }
                    if (pg + 8 < P_OUT) {
                        ob[8]         = acc[mf][nf][2] + b0;
                        ob[P_OUT + 8] = acc[mf][nf][3] + b1;
                    }
                    #pragma unroll
                    for (int i = 0; i < 4; ++i) acc[mf][nf][i] = 0.0f;
                }
            }
        }
        tile = ntile;
    }
}

extern "C" void kernel_launch(void* const* d_in, const int* in_sizes, int n_in,
                              void* d_out, int out_size)
{
    const float* x  = (const float*)d_in[0];   // (8, 128, 32768)
    const float* W  = (const float*)d_in[1];   // (128, 128, 2)
    const float* bs = (const float*)d_in[2];   // (128,)
    float* out = (float*)d_out;                // (8, 128, 32769)

    cudaFuncSetAttribute(dconv6, cudaFuncAttributeMaxDynamicSharedMemorySize, SM_TOT);

    prep_W<<<64, 256>>>(W);
    dconv6<<<GRIDX, 512, SM_TOT>>>(x, bs, out);
}